// round 3
// baseline (speedup 1.0000x reference)
#include <cuda_runtime.h>
#include <cstdint>

// ----------------------------------------------------------------------------
// BlockLinear on GB300 via legacy mma.sync tf32 (compute_103 target: no tcgen05).
// out[4096, 64*256] = blockdiag(w) @ x + bias
//   x: [4096, 16384] f32, w: [64, 256, 256] f32 (n-major, k contiguous), bias f32
// CTA tile: M=128 x N=256, K=256 in 8 chunks of 32. cp.async 4-stage pipeline,
// padded smem rows (36 floats) for conflict-free fragment loads.
// 512 threads = 16 warps (2 m x 8 n), warp tile 64x32, mma m16n8k8 tf32.
// ----------------------------------------------------------------------------

#define NBLK    64
#define INB     256
#define OUTB    256
#define BATCHSZ 4096
#define ROWF    (NBLK * INB)   // 16384

#define MT      128
#define NT      256
#define KC      32
#define NCHUNK  (INB / KC)     // 8
#define NSTAGE  4
#define PRE     (NSTAGE - 1)

#define PADF    36                       // padded floats per smem row (132..144B)
#define A_BYTES (MT * PADF * 4)          // 18432
#define B_BYTES (NT * PADF * 4)          // 36864
#define STAGE_BYTES (A_BYTES + B_BYTES)  // 55296
#define SM_BIAS  0
#define SM_TILES 1024
#define SMEM_TOTAL (SM_TILES + NSTAGE * STAGE_BYTES)   // 222208

// ---------------- device helpers ----------------

__device__ __forceinline__ uint32_t smem_u32(const void* p) {
    uint32_t a;
    asm("{ .reg .u64 t; cvta.to.shared.u64 t, %1; cvt.u32.u64 %0, t; }" : "=r"(a) : "l"(p));
    return a;
}

__device__ __forceinline__ void cp16(uint32_t dst, const void* src) {
    asm volatile("cp.async.ca.shared.global [%0], [%1], 16;" :: "r"(dst), "l"(src));
}

__device__ __forceinline__ uint32_t f2tf32(float f) {
    uint32_t r;
    asm("cvt.rna.tf32.f32 %0, %1;" : "=r"(r) : "f"(f));
    return r;
}

__device__ __forceinline__ void mma_tf32(float* c, const uint32_t* a, const uint32_t* b) {
    asm volatile(
        "mma.sync.aligned.m16n8k8.row.col.f32.tf32.tf32.f32 "
        "{%0,%1,%2,%3}, {%4,%5,%6,%7}, {%8,%9}, {%0,%1,%2,%3};"
        : "+f"(c[0]), "+f"(c[1]), "+f"(c[2]), "+f"(c[3])
        : "r"(a[0]), "r"(a[1]), "r"(a[2]), "r"(a[3]), "r"(b[0]), "r"(b[1]));
}

// ---------------- kernel ----------------

__global__ void __launch_bounds__(512, 1)
blocklinear_mma_kernel(const float* __restrict__ x,
                       const float* __restrict__ w,
                       const float* __restrict__ bias,
                       float* __restrict__ out) {
    extern __shared__ char smem[];
    uint32_t sbase = smem_u32(smem);
    const int tid = threadIdx.x;
    const int blk   = blockIdx.x;   // 0..63   (weight block / 256-col slice of x)
    const int mtile = blockIdx.y;   // 0..31   (128-row batch slice)

    // bias tile -> smem
    if (tid < NT)
        reinterpret_cast<float*>(smem + SM_BIAS)[tid] = bias[blk * OUTB + tid];

    const int wid  = tid >> 5;
    const int lane = tid & 31;
    const int gID  = lane >> 2;     // group id (0..7)
    const int tig  = lane & 3;      // thread in group
    const int wm   = wid >> 3;      // 0..1  -> 64-row strip
    const int wn   = wid & 7;       // 0..7  -> 32-col strip

    // stage loader: A tile [128 x 32] + B tile [256 x 32], 16B cp.async each
    auto load_stage = [&](int kc, int s) {
        const uint32_t sA = sbase + SM_TILES + s * STAGE_BYTES;
        const uint32_t sB = sA + A_BYTES;
        const int kcol = kc * KC;
#pragma unroll
        for (int it = 0; it < 2; it++) {          // 1024 chunks / 512 thr
            int id  = tid + it * 512;
            int row = id >> 3, c4 = id & 7;
            const float* g = x + (size_t)(mtile * MT + row) * ROWF
                               + blk * INB + kcol + c4 * 4;
            cp16(sA + row * (PADF * 4) + c4 * 16, g);
        }
#pragma unroll
        for (int it = 0; it < 4; it++) {          // 2048 chunks / 512 thr
            int id  = tid + it * 512;
            int row = id >> 3, c4 = id & 7;
            const float* g = w + ((size_t)blk * OUTB + row) * INB + kcol + c4 * 4;
            cp16(sB + row * (PADF * 4) + c4 * 16, g);
        }
    };

    // prologue: prefetch PRE stages
#pragma unroll
    for (int s = 0; s < PRE; s++) {
        load_stage(s, s);
        asm volatile("cp.async.commit_group;" ::: "memory");
    }

    float acc[4][4][4];
#pragma unroll
    for (int i = 0; i < 4; i++)
#pragma unroll
        for (int j = 0; j < 4; j++)
#pragma unroll
            for (int r = 0; r < 4; r++) acc[i][j][r] = 0.0f;

    for (int kc = 0; kc < NCHUNK; kc++) {
        asm volatile("cp.async.wait_group %0;" :: "n"(PRE - 1) : "memory");
        __syncthreads();

        // prefetch next stage (overlaps with compute below)
        if (kc + PRE < NCHUNK) load_stage(kc + PRE, (kc + PRE) & (NSTAGE - 1));
        asm volatile("cp.async.commit_group;" ::: "memory");

        const int s = kc & (NSTAGE - 1);
        const float* As = reinterpret_cast<const float*>(smem + SM_TILES + s * STAGE_BYTES);
        const float* Bs = reinterpret_cast<const float*>(smem + SM_TILES + s * STAGE_BYTES + A_BYTES);

#pragma unroll
        for (int ks = 0; ks < KC / 8; ks++) {
            const int kk = ks * 8 + tig;
            uint32_t a[4][4], b[4][2];
#pragma unroll
            for (int i = 0; i < 4; i++) {
                int r0 = wm * 64 + i * 16 + gID;
                a[i][0] = f2tf32(As[r0 * PADF + kk]);
                a[i][1] = f2tf32(As[(r0 + 8) * PADF + kk]);
                a[i][2] = f2tf32(As[r0 * PADF + kk + 4]);
                a[i][3] = f2tf32(As[(r0 + 8) * PADF + kk + 4]);
            }
#pragma unroll
            for (int j = 0; j < 4; j++) {
                int n0 = wn * 32 + j * 8 + gID;
                b[j][0] = f2tf32(Bs[n0 * PADF + kk]);
                b[j][1] = f2tf32(Bs[n0 * PADF + kk + 4]);
            }
#pragma unroll
            for (int i = 0; i < 4; i++)
#pragma unroll
                for (int j = 0; j < 4; j++)
                    mma_tf32(acc[i][j], a[i], b[j]);
        }
    }

    // epilogue: bias + store (float2, 8B aligned)
    const float* bsm = reinterpret_cast<const float*>(smem + SM_BIAS);
#pragma unroll
    for (int i = 0; i < 4; i++) {
        const int row0 = mtile * MT + wm * 64 + i * 16 + gID;
#pragma unroll
        for (int j = 0; j < 4; j++) {
            const int colL = wn * 32 + j * 8 + tig * 2;
            const int colG = blk * OUTB + colL;
            float2 v0, v1;
            v0.x = acc[i][j][0] + bsm[colL];
            v0.y = acc[i][j][1] + bsm[colL + 1];
            v1.x = acc[i][j][2] + bsm[colL];
            v1.y = acc[i][j][3] + bsm[colL + 1];
            *reinterpret_cast<float2*>(out + (size_t)row0 * ROWF + colG) = v0;
            *reinterpret_cast<float2*>(out + (size_t)(row0 + 8) * ROWF + colG) = v1;
        }
    }
}

// ---------------- host ----------------

extern "C" void kernel_launch(void* const* d_in, const int* in_sizes, int n_in,
                              void* d_out, int out_size) {
    const float* x    = (const float*)d_in[0];
    const float* w    = (const float*)d_in[1];
    const float* bias = (const float*)d_in[2];
    float* out        = (float*)d_out;

    static bool attr_done = false;
    if (!attr_done) {
        cudaFuncSetAttribute(blocklinear_mma_kernel,
                             cudaFuncAttributeMaxDynamicSharedMemorySize, SMEM_TOTAL);
        attr_done = true;
    }

    dim3 grid(NBLK, BATCHSZ / MT);   // (64, 32): mtile slow -> x L2 reuse per wave
    blocklinear_mma_kernel<<<grid, 512, SMEM_TOTAL>>>(x, w, bias, out);
}